// round 13
// baseline (speedup 1.0000x reference)
#include <cuda_runtime.h>
#include <cuda_bf16.h>
#include <cuda_fp16.h>
#include <cstdint>
#include <math.h>

// Problem constants
#define BATCH 8
#define NTOK  4096
#define CDIM  768

// ---------------------------------------------------------------------------
// device scratch (no runtime allocation allowed)
// ---------------------------------------------------------------------------
__device__ __align__(16) __half g_Ah[(size_t)BATCH * NTOK * CDIM];   // [32768][768] fp16 x
__device__ __align__(16) __half g_Bh[(size_t)CDIM * CDIM];           // [768 n][768 k] fp16 M^T
__device__ __align__(16) __half g_Uh[(size_t)BATCH * 64 * 128 * CDIM]; // [(b,q,k)][768] fp16 U
__device__ __align__(16) __half g_T1h[128 * 64];                     // [i][s] i<64: cos(i*s), else sin
__device__ __align__(16) __half g_T2h[64 * 128];                     // [p][k] k<64: cos(p*k), else -sin

// ---------------------------------------------------------------------------
// PTX helpers (baseline compute_103-safe)
// ---------------------------------------------------------------------------
__device__ __forceinline__ uint32_t smem_u32(const void* p) {
    uint32_t a;
    asm("{ .reg .u64 t; cvta.to.shared.u64 t, %1; cvt.u32.u64 %0, t; }" : "=r"(a) : "l"(p));
    return a;
}
__device__ __forceinline__ void cp_async16(uint32_t sa, const void* ga) {
    asm volatile("cp.async.cg.shared.global [%0], [%1], 16;" :: "r"(sa), "l"(ga));
}
#define CP_COMMIT() asm volatile("cp.async.commit_group;" ::: "memory")
#define CP_WAIT2()  asm volatile("cp.async.wait_group 2;" ::: "memory")
#define CP_WAIT1()  asm volatile("cp.async.wait_group 1;" ::: "memory")
#define CP_WAIT0()  asm volatile("cp.async.wait_group 0;" ::: "memory")
#define SWZ128(o)   ((o) ^ (((o) >> 3) & 0x70))
#define SWZ256(o)   ((o) ^ (((o) >> 4) & 0x70))

__device__ __forceinline__ void ldmx4(uint32_t* r, uint32_t addr) {
    asm volatile("ldmatrix.sync.aligned.m8n8.x4.shared.b16 {%0,%1,%2,%3}, [%4];"
                 : "=r"(r[0]), "=r"(r[1]), "=r"(r[2]), "=r"(r[3]) : "r"(addr));
}
__device__ __forceinline__ void ldmx4t(uint32_t* r, uint32_t addr) {
    asm volatile("ldmatrix.sync.aligned.m8n8.x4.trans.shared.b16 {%0,%1,%2,%3}, [%4];"
                 : "=r"(r[0]), "=r"(r[1]), "=r"(r[2]), "=r"(r[3]) : "r"(addr));
}
__device__ __forceinline__ void mma16816h(float* d, const uint32_t* a, uint32_t b0, uint32_t b1) {
    asm volatile("mma.sync.aligned.m16n8k16.row.col.f32.f16.f16.f32 "
                 "{%0,%1,%2,%3},{%4,%5,%6,%7},{%8,%9},{%0,%1,%2,%3};"
                 : "+f"(d[0]), "+f"(d[1]), "+f"(d[2]), "+f"(d[3])
                 : "r"(a[0]), "r"(a[1]), "r"(a[2]), "r"(a[3]), "r"(b0), "r"(b1));
}

#define STG1_ROWH 264   /* 528B row stride (odd multiple of 16B): conflict-free */

// ---------------------------------------------------------------------------
// 0) fp16 twiddle tables
// ---------------------------------------------------------------------------
__global__ void init_tables_kernel() {
    int tid = threadIdx.x;
    const double TWO_PI = 6.283185307179586476925286766559;
    for (int i = tid; i < 128 * 64; i += 256) {
        int row = i >> 6, s = i & 63;
        double ang = TWO_PI * (double)(((row & 63) * s) & 63) / 64.0;
        float v = (row < 64) ? (float)cos(ang) : (float)sin(ang);
        g_T1h[i] = __float2half_rn(v);
    }
    for (int i = tid; i < 64 * 128; i += 256) {
        int p = i >> 7, k = i & 127;
        double ang = TWO_PI * (double)((p * (k & 63)) & 63) / 64.0;
        float v = (k < 64) ? (float)cos(ang) : (float)(-sin(ang));
        g_T2h[i] = __float2half_rn(v);
    }
}

// ---------------------------------------------------------------------------
// 1) Direct B build: g_Bh[n][k] = fp16( sum_j proj_w[n][j] * qkv_w[2C+j][k] )
//    64x64 tile, 4x4 micro, 256 threads. Both operands coalesced; no g_M.
// ---------------------------------------------------------------------------
__global__ __launch_bounds__(256) void compute_B_kernel(
    const float* __restrict__ qkv_w, const float* __restrict__ proj_w)
{
    __shared__ float sA[16][68];   // [jj][nn]  A[n][j] = proj_w[n][j]
    __shared__ float sB[16][68];   // [jj][kk]  B[j][k] = qkv_w[2C+j][k]
    int n0 = blockIdx.y * 64, k0 = blockIdx.x * 64;
    int tid = threadIdx.x;
    int ty = (tid >> 4) << 2, tx = (tid & 15) << 2;
    float acc[4][4];
#pragma unroll
    for (int i = 0; i < 4; i++)
#pragma unroll
        for (int j = 0; j < 4; j++) acc[i][j] = 0.f;

    for (int j0 = 0; j0 < CDIM; j0 += 16) {
        {
            int nn = tid >> 2, jq = (tid & 3) * 4;
            float4 v = *(const float4*)(proj_w + (size_t)(n0 + nn) * CDIM + j0 + jq);
            sA[jq + 0][nn] = v.x; sA[jq + 1][nn] = v.y;
            sA[jq + 2][nn] = v.z; sA[jq + 3][nn] = v.w;
        }
#pragma unroll
        for (int c = 0; c < 4; c++) {
            int e = tid + c * 256;
            int jj = e >> 6, kk = e & 63;
            sB[jj][kk] = qkv_w[(size_t)(2 * CDIM + j0 + jj) * CDIM + k0 + kk];
        }
        __syncthreads();
#pragma unroll
        for (int jj = 0; jj < 16; jj++) {
            float a[4], b[4];
            *(float4*)a = *(const float4*)&sA[jj][ty];
            *(float4*)b = *(const float4*)&sB[jj][tx];
#pragma unroll
            for (int i = 0; i < 4; i++)
#pragma unroll
                for (int j = 0; j < 4; j++)
                    acc[i][j] += a[i] * b[j];
        }
        __syncthreads();
    }
#pragma unroll
    for (int i = 0; i < 4; i++) {
        __half2 h0 = __floats2half2_rn(acc[i][0], acc[i][1]);
        __half2 h1 = __floats2half2_rn(acc[i][2], acc[i][3]);
        __half2* dst = (__half2*)(g_Bh + (size_t)(n0 + ty + i) * CDIM + k0 + tx);
        dst[0] = h0; dst[1] = h1;
    }
}

// ---------------------------------------------------------------------------
// 2) x -> fp16 (8 floats -> 16B store per thread)
// ---------------------------------------------------------------------------
__global__ __launch_bounds__(256) void prep_a_kernel(const float* __restrict__ x) {
    size_t i8 = ((size_t)blockIdx.x * 256 + threadIdx.x) * 8;
    if (i8 >= (size_t)BATCH * NTOK * CDIM) return;
    float4 v0 = *(const float4*)(x + i8);
    float4 v1 = *(const float4*)(x + i8 + 4);
    __half2 h[4];
    h[0] = __floats2half2_rn(v0.x, v0.y);
    h[1] = __floats2half2_rn(v0.z, v0.w);
    h[2] = __floats2half2_rn(v1.x, v1.y);
    h[3] = __floats2half2_rn(v1.z, v1.w);
    *(uint4*)(g_Ah + i8) = *(uint4*)h;
}

// ---------------------------------------------------------------------------
// 3) Fused GEMM + pass1. CTA tile 128(M) x 256(N), K-tile 64, 4-stage ring.
//    512 threads, 16 warps as 4m x 4n, warp tile 32x64.
//    Epilogue: Z fp16 -> smem stage -> fused U = T1 * Z -> g_Uh.
// ---------------------------------------------------------------------------
#define GM_NT 12
#define STG_BYTES 49152          /* A 16KB + B 32KB per stage */
#define NSTAGE 4
#define GM_SMEM (NSTAGE * STG_BYTES + 16384)   /* + T1 (16KB) */
#define GM_THREADS 512

__device__ __forceinline__ void gemm_load_tile(uint32_t sb, int tid, int bm, int bn,
                                               int kt, int slot) {
    int koff = kt * 64;
    uint32_t abase = sb + slot * STG_BYTES;
    uint32_t bbase = abase + 16384;
#pragma unroll
    for (int c = 0; c < 2; c++) {
        int ch = tid + c * GM_THREADS;        // 0..1023: 128 rows x 8 chunks
        int row = ch >> 3, kc = ch & 7;
        cp_async16(abase + SWZ128(row * 128 + kc * 16),
                   g_Ah + (size_t)(bm + row) * CDIM + koff + kc * 8);
    }
#pragma unroll
    for (int c = 0; c < 4; c++) {
        int ch = tid + c * GM_THREADS;        // 0..2047: 256 rows x 8 chunks
        int row = ch >> 3, kc = ch & 7;
        cp_async16(bbase + SWZ128(row * 128 + kc * 16),
                   g_Bh + (size_t)(bn + row) * CDIM + koff + kc * 8);
    }
}

__global__ __launch_bounds__(GM_THREADS) void gemm_mma_kernel() {
    extern __shared__ char smem[];
    uint32_t sb = smem_u32(smem);
    uint32_t sbT1 = sb + NSTAGE * STG_BYTES;
    __half* stage1 = (__half*)smem;                             // Z tile 128x264 (67584B)
    __half* stage2 = (__half*)(smem + 128 * STG1_ROWH * 2);     // U tile 128x264 (67584B)
    uint32_t sbS1 = sb;
    int tid = threadIdx.x;
    int wid = tid >> 5, lane = tid & 31;
    int wm = wid >> 2, wn = wid & 3;          // 4m x 4n
    int bm = blockIdx.y * 128;
    int bn = blockIdx.x * 256;
    int b = bm >> 12;                 // batch
    int r0 = (bm >> 6) & 63;          // first spatial row of this tile

    int l7 = lane & 7, sel = lane >> 3;
    int rsel = (sel & 1) * 8;
    int csel = (sel >> 1) * 16;
    int g1 = (lane >> 3) & 1;
    int g2 = (lane >> 4) * 16;

    float acc[2][8][4];
#pragma unroll
    for (int i = 0; i < 2; i++)
#pragma unroll
        for (int j = 0; j < 8; j++)
#pragma unroll
            for (int v = 0; v < 4; v++) acc[i][j][v] = 0.f;

    // prologue: T1 + tile0 in group 0; tiles 1,2 in groups 1,2
#pragma unroll
    for (int c = 0; c < 2; c++) {
        int o = (tid + c * GM_THREADS) * 16;  // 0..16383
        cp_async16(sbT1 + SWZ128(o), (const char*)g_T1h + o);
    }
    gemm_load_tile(sb, tid, bm, bn, 0, 0);
    CP_COMMIT();
    gemm_load_tile(sb, tid, bm, bn, 1, 1);
    CP_COMMIT();
    gemm_load_tile(sb, tid, bm, bn, 2, 2);
    CP_COMMIT();

    for (int kt = 0; kt < GM_NT; kt++) {
        CP_WAIT2();
        __syncthreads();

        if (kt + NSTAGE - 1 < GM_NT)
            gemm_load_tile(sb, tid, bm, bn, kt + NSTAGE - 1, (kt + NSTAGE - 1) & (NSTAGE - 1));
        CP_COMMIT();

        uint32_t ab = sb + (kt & (NSTAGE - 1)) * STG_BYTES;
        uint32_t bb = ab + 16384;
#pragma unroll
        for (int ks = 0; ks < 4; ks++) {
            uint32_t afrag[2][4];
#pragma unroll
            for (int mt = 0; mt < 2; mt++) {
                int row = wm * 32 + mt * 16 + l7 + rsel;
                ldmx4(afrag[mt], ab + SWZ128(row * 128 + ks * 32 + csel));
            }
#pragma unroll
            for (int nt = 0; nt < 4; nt++) {
                uint32_t bfrag[4];
                int row = wn * 64 + nt * 16 + l7 + rsel;
                ldmx4(bfrag, bb + SWZ128(row * 128 + ks * 32 + csel));
#pragma unroll
                for (int mt = 0; mt < 2; mt++) {
                    mma16816h(acc[mt][nt * 2 + 0], afrag[mt], bfrag[0], bfrag[2]);
                    mma16816h(acc[mt][nt * 2 + 1], afrag[mt], bfrag[1], bfrag[3]);
                }
            }
        }
    }

    // ---- stage Z (fp16) into stage1 ----
    CP_WAIT0();
    __syncthreads();
    int rq = lane >> 2, cq = (lane & 3) * 2;
#pragma unroll
    for (int mt = 0; mt < 2; mt++) {
#pragma unroll
        for (int n8 = 0; n8 < 8; n8++) {
            float* d = acc[mt][n8];
            int row = wm * 32 + mt * 16 + rq;
            int c = wn * 64 + n8 * 8 + cq;
            *(__half2*)&stage1[row * STG1_ROWH + c] = __floats2half2_rn(d[0], d[1]);
            *(__half2*)&stage1[(row + 8) * STG1_ROWH + c] = __floats2half2_rn(d[2], d[3]);
        }
    }
    __syncthreads();

    // ---- fused pass1: per half h (spatial row r0+h): U[128i x 256ch] = T1 * Z_h ----
#pragma unroll
    for (int h = 0; h < 2; h++) {
        float uacc[2][8][4];
#pragma unroll
        for (int i = 0; i < 2; i++)
#pragma unroll
            for (int j = 0; j < 8; j++)
#pragma unroll
                for (int v = 0; v < 4; v++) uacc[i][j][v] = 0.f;

#pragma unroll
        for (int ks = 0; ks < 4; ks++) {
            uint32_t afrag[2][4];
#pragma unroll
            for (int mt = 0; mt < 2; mt++) {
                int row = wm * 32 + mt * 16 + l7 + rsel;
                ldmx4(afrag[mt], sbT1 + SWZ128(row * 128 + ks * 32 + csel));
            }
#pragma unroll
            for (int ng = 0; ng < 4; ng++) {
                uint32_t bfrag[4];
                int srow = h * 64 + ks * 16 + l7 + g1 * 8;
                int colb = wn * 128 + ng * 32 + g2;
                ldmx4t(bfrag, sbS1 + srow * (STG1_ROWH * 2) + colb);
#pragma unroll
                for (int mt = 0; mt < 2; mt++) {
                    mma16816h(uacc[mt][ng * 2 + 0], afrag[mt], bfrag[0], bfrag[1]);
                    mma16816h(uacc[mt][ng * 2 + 1], afrag[mt], bfrag[2], bfrag[3]);
                }
            }
        }

        if (h == 1) __syncthreads();      // prior stage2 store-read complete
#pragma unroll
        for (int mt = 0; mt < 2; mt++) {
#pragma unroll
            for (int n8 = 0; n8 < 8; n8++) {
                float* d = uacc[mt][n8];
                int i0 = wm * 32 + mt * 16 + rq;
                int chl = wn * 64 + n8 * 8 + cq;
                *(__half2*)&stage2[i0 * STG1_ROWH + chl] = __floats2half2_rn(d[0], d[1]);
                *(__half2*)&stage2[(i0 + 8) * STG1_ROWH + chl] = __floats2half2_rn(d[2], d[3]);
            }
        }
        __syncthreads();
        int r = r0 + h;
#pragma unroll
        for (int it = 0; it < 8; it++) {
            int idx = tid + it * GM_THREADS;      // 0..4095: 128 rows x 32 chunks
            int row = idx >> 5, ck = idx & 31;
            int q = row & 63;
            int kk = (row < 64) ? r : 64 + r;
            uint4 v = *(uint4*)&stage2[row * STG1_ROWH + ck * 8];
            *(uint4*)(g_Uh + ((size_t)(b * 64 + q) * 128 + kk) * CDIM + bn + ck * 8) = v;
        }
    }
}

// ---------------------------------------------------------------------------
// 4) Pass 2 (fp16 mma): per (b, q): out[64p x ch] = T2 * U + bias,
//    looping over all 6 channel tiles with double-buffered B.
// ---------------------------------------------------------------------------
#define P2_SMEM (16384 + 2 * 32768)

__global__ __launch_bounds__(256) void pass2_kernel(
    const float* __restrict__ bias, float* __restrict__ out)
{
    extern __shared__ char smem[];
    uint32_t sb = smem_u32(smem);
    uint32_t sbA = sb;
    int b = blockIdx.y, q = blockIdx.x;
    int tid = threadIdx.x;
    int wid = tid >> 5, lane = tid & 31;
    int wm = wid >> 2, wn = wid & 3;

    const __half* usrc = g_Uh + (size_t)(b * 64 + q) * 128 * CDIM;

    // prologue: A (T2) + B tile 0 -> group 0
#pragma unroll
    for (int c = 0; c < 4; c++) {
        int idx = tid + c * 256;
        int p = idx >> 4, ck = idx & 15;
        cp_async16(sbA + SWZ256(p * 256 + ck * 16), g_T2h + p * 128 + ck * 8);
    }
#pragma unroll
    for (int c = 0; c < 8; c++) {
        int idx = tid + c * 256;
        int k = idx >> 4, ck = idx & 15;
        cp_async16(sb + 16384 + SWZ256(k * 256 + ck * 16),
                   usrc + (size_t)k * CDIM + 0 + ck * 8);
    }
    CP_COMMIT();

    int l7 = lane & 7, sel = lane >> 3;
    int rsel = (sel & 1) * 8;
    int csel = (sel >> 1) * 16;
    int g1 = (lane >> 3) & 1;
    int g2 = (lane >> 4) * 16;

    for (int cht = 0; cht < 6; cht++) {
        __syncthreads();
        if (cht + 1 < 6) {
            uint32_t bbuf = sb + 16384 + ((cht + 1) & 1) * 32768;
            int c1 = (cht + 1) * 128;
#pragma unroll
            for (int c = 0; c < 8; c++) {
                int idx = tid + c * 256;
                int k = idx >> 4, ck = idx & 15;
                cp_async16(bbuf + SWZ256(k * 256 + ck * 16),
                           usrc + (size_t)k * CDIM + c1 + ck * 8);
            }
            CP_COMMIT();
            CP_WAIT1();
        } else {
            CP_WAIT0();
        }
        __syncthreads();

        uint32_t sbB = sb + 16384 + (cht & 1) * 32768;
        int c0 = cht * 128;

        float acc[2][4][4];
#pragma unroll
        for (int i = 0; i < 2; i++)
#pragma unroll
            for (int j = 0; j < 4; j++)
#pragma unroll
                for (int v = 0; v < 4; v++) acc[i][j][v] = 0.f;

#pragma unroll
        for (int ks = 0; ks < 8; ks++) {
            uint32_t afrag[2][4];
#pragma unroll
            for (int mt = 0; mt < 2; mt++) {
                int row = wm * 32 + mt * 16 + l7 + rsel;
                ldmx4(afrag[mt], sbA + SWZ256(row * 256 + ks * 32 + csel));
            }
#pragma unroll
            for (int ng = 0; ng < 2; ng++) {
                uint32_t bfrag[4];
                int row = ks * 16 + l7 + g1 * 8;
                int colb = wn * 64 + ng * 32 + g2;
                ldmx4t(bfrag, sbB + SWZ256(row * 256 + colb));
#pragma unroll
                for (int mt = 0; mt < 2; mt++) {
                    mma16816h(acc[mt][ng * 2 + 0], afrag[mt], bfrag[0], bfrag[1]);
                    mma16816h(acc[mt][ng * 2 + 1], afrag[mt], bfrag[2], bfrag[3]);
                }
            }
        }

        int rq = lane >> 2, cq = (lane & 3) * 2;
#pragma unroll
        for (int mt = 0; mt < 2; mt++) {
            int pbase = wm * 32 + mt * 16;
#pragma unroll
            for (int n8 = 0; n8 < 4; n8++) {
                float* d = acc[mt][n8];
                int ch = c0 + wn * 32 + n8 * 8 + cq;
                float2 bv = *(const float2*)(bias + ch);
                int p0 = pbase + rq, p1 = pbase + rq + 8;
                float* o0 = out + ((size_t)b * NTOK + p0 * 64 + q) * CDIM + ch;
                float* o1 = out + ((size_t)b * NTOK + p1 * 64 + q) * CDIM + ch;
                *(float2*)o0 = make_float2(d[0] + bv.x, d[1] + bv.y);
                *(float2*)o1 = make_float2(d[2] + bv.x, d[3] + bv.y);
            }
        }
    }
}

// ---------------------------------------------------------------------------
// launch
// ---------------------------------------------------------------------------
extern "C" void kernel_launch(void* const* d_in, const int* in_sizes, int n_in,
                              void* d_out, int out_size)
{
    const float* x      = (const float*)d_in[0];   // [8,4096,768]
    const float* qkv_w  = (const float*)d_in[1];   // [2304,768]
    const float* proj_w = (const float*)d_in[2];   // [768,768]
    const float* proj_b = (const float*)d_in[3];   // [768]
    float* out = (float*)d_out;

    cudaFuncSetAttribute(gemm_mma_kernel, cudaFuncAttributeMaxDynamicSharedMemorySize, GM_SMEM);
    cudaFuncSetAttribute(pass2_kernel,    cudaFuncAttributeMaxDynamicSharedMemorySize, P2_SMEM);

    init_tables_kernel<<<1, 256>>>();
    compute_B_kernel<<<dim3(CDIM / 64, CDIM / 64), 256>>>(qkv_w, proj_w);
    prep_a_kernel<<<(int)(((size_t)BATCH * NTOK * CDIM / 8 + 255) / 256), 256>>>(x);
    gemm_mma_kernel<<<dim3(CDIM / 256, (BATCH * NTOK) / 128), GM_THREADS, GM_SMEM>>>();
    pass2_kernel<<<dim3(64, BATCH), 256, P2_SMEM>>>(proj_b, out);
}

// round 14
// speedup vs baseline: 1.4586x; 1.4586x over previous
#include <cuda_runtime.h>
#include <cuda_bf16.h>
#include <cuda_fp16.h>
#include <cstdint>
#include <math.h>

// Problem constants
#define BATCH 8
#define NTOK  4096
#define CDIM  768

// ---------------------------------------------------------------------------
// device scratch (no runtime allocation allowed)
// ---------------------------------------------------------------------------
__device__ __align__(16) __half g_Ah[(size_t)BATCH * NTOK * CDIM];   // [32768][768] fp16 x
__device__ __align__(16) __half g_Bh[(size_t)CDIM * CDIM];           // [768 n][768 k] fp16 M^T
__device__ __align__(16) __half g_Uh[(size_t)BATCH * 64 * 128 * CDIM]; // [(b,q,k)][768] fp16 U
__device__ __align__(16) __half g_T1h[128 * 64];                     // [i][s] i<64: cos(i*s), else sin
__device__ __align__(16) __half g_T2h[64 * 128];                     // [p][k] k<64: cos(p*k), else -sin
__device__ __align__(16) __nv_bfloat16 g_Wp[(size_t)CDIM * 2 * CDIM];   // [768 n][1536]: proj hi|lo
__device__ __align__(16) __nv_bfloat16 g_Wq[(size_t)2 * CDIM * CDIM];   // [chunk][768 j][768 k]: qkv-v hi,lo

// ---------------------------------------------------------------------------
// PTX helpers (baseline compute_103-safe)
// ---------------------------------------------------------------------------
__device__ __forceinline__ uint32_t smem_u32(const void* p) {
    uint32_t a;
    asm("{ .reg .u64 t; cvta.to.shared.u64 t, %1; cvt.u32.u64 %0, t; }" : "=r"(a) : "l"(p));
    return a;
}
__device__ __forceinline__ void cp_async16(uint32_t sa, const void* ga) {
    asm volatile("cp.async.cg.shared.global [%0], [%1], 16;" :: "r"(sa), "l"(ga));
}
#define CP_COMMIT() asm volatile("cp.async.commit_group;" ::: "memory")
#define CP_WAIT2()  asm volatile("cp.async.wait_group 2;" ::: "memory")
#define CP_WAIT1()  asm volatile("cp.async.wait_group 1;" ::: "memory")
#define CP_WAIT0()  asm volatile("cp.async.wait_group 0;" ::: "memory")
#define SWZ128(o)   ((o) ^ (((o) >> 3) & 0x70))
#define SWZ256(o)   ((o) ^ (((o) >> 4) & 0x70))

__device__ __forceinline__ void ldmx4(uint32_t* r, uint32_t addr) {
    asm volatile("ldmatrix.sync.aligned.m8n8.x4.shared.b16 {%0,%1,%2,%3}, [%4];"
                 : "=r"(r[0]), "=r"(r[1]), "=r"(r[2]), "=r"(r[3]) : "r"(addr));
}
__device__ __forceinline__ void ldmx4t(uint32_t* r, uint32_t addr) {
    asm volatile("ldmatrix.sync.aligned.m8n8.x4.trans.shared.b16 {%0,%1,%2,%3}, [%4];"
                 : "=r"(r[0]), "=r"(r[1]), "=r"(r[2]), "=r"(r[3]) : "r"(addr));
}
__device__ __forceinline__ void mma16816h(float* d, const uint32_t* a, uint32_t b0, uint32_t b1) {
    asm volatile("mma.sync.aligned.m16n8k16.row.col.f32.f16.f16.f32 "
                 "{%0,%1,%2,%3},{%4,%5,%6,%7},{%8,%9},{%0,%1,%2,%3};"
                 : "+f"(d[0]), "+f"(d[1]), "+f"(d[2]), "+f"(d[3])
                 : "r"(a[0]), "r"(a[1]), "r"(a[2]), "r"(a[3]), "r"(b0), "r"(b1));
}
__device__ __forceinline__ void mma16816b(float* d, const uint32_t* a, uint32_t b0, uint32_t b1) {
    asm volatile("mma.sync.aligned.m16n8k16.row.col.f32.bf16.bf16.f32 "
                 "{%0,%1,%2,%3},{%4,%5,%6,%7},{%8,%9},{%0,%1,%2,%3};"
                 : "+f"(d[0]), "+f"(d[1]), "+f"(d[2]), "+f"(d[3])
                 : "r"(a[0]), "r"(a[1]), "r"(a[2]), "r"(a[3]), "r"(b0), "r"(b1));
}

#define STG1_ROWH 264   /* 528B row stride (odd multiple of 16B): conflict-free */

// ---------------------------------------------------------------------------
// 0) fp16 twiddle tables via 64-entry base lookup (identical values to before)
// ---------------------------------------------------------------------------
__global__ void init_tables_kernel() {
    __shared__ float cb[64], sb_[64];
    int tid = threadIdx.x;
    const double TWO_PI = 6.283185307179586476925286766559;
    if (tid < 64) {
        double ang = TWO_PI * (double)tid / 64.0;
        cb[tid] = (float)cos(ang);
        sb_[tid] = (float)sin(ang);
    }
    __syncthreads();
    for (int i = tid; i < 128 * 64; i += 256) {
        int row = i >> 6, s = i & 63;
        int idx = ((row & 63) * s) & 63;
        g_T1h[i] = __float2half_rn((row < 64) ? cb[idx] : sb_[idx]);
    }
    for (int i = tid; i < 64 * 128; i += 256) {
        int p = i >> 7, k = i & 127;
        int idx = (p * (k & 63)) & 63;
        g_T2h[i] = __float2half_rn((k < 64) ? cb[idx] : -sb_[idx]);
    }
}

// ---------------------------------------------------------------------------
// 1a) split weights into bf16 hi/lo for the B-build GEMM
//     g_Wp[n][j] = hi(proj_w[n][j]), g_Wp[n][768+j] = lo
//     g_Wq[0][j][k] = hi(qkv_w[2C+j][k]), g_Wq[1][j][k] = lo
// ---------------------------------------------------------------------------
__global__ __launch_bounds__(256) void prep_w_kernel(
    const float* __restrict__ qkv_w, const float* __restrict__ proj_w)
{
    int i = blockIdx.x * 256 + threadIdx.x;
    if (i >= CDIM * CDIM) return;
    int r = i / CDIM, c = i % CDIM;
    {
        float v = proj_w[i];
        __nv_bfloat16 h = __float2bfloat16(v);
        g_Wp[(size_t)r * 1536 + c] = h;
        g_Wp[(size_t)r * 1536 + 768 + c] = __float2bfloat16(v - __bfloat162float(h));
    }
    {
        float v = qkv_w[(size_t)(2 * CDIM + r) * CDIM + c];
        __nv_bfloat16 h = __float2bfloat16(v);
        g_Wq[i] = h;
        g_Wq[(size_t)CDIM * CDIM + i] = __float2bfloat16(v - __bfloat162float(h));
    }
}

// ---------------------------------------------------------------------------
// 1b) B build via bf16 split 3-term mma GEMM:
//     g_Bh[n][k] = fp16( sum_j proj_w[n][j] * qkv_w[2C+j][k] )
//     CTA 128(n) x 128(k), K logical 2304 (Ph*Qh | Ph*Ql | Pl*Qh), 36 K-tiles.
//     8 warps (4m x 2n), warp 32x64. 2-stage cp.async ring.
// ---------------------------------------------------------------------------
#define CB_SMEM (2 * 32768)

__device__ __forceinline__ void cb_load_tile(uint32_t sb, int tid, int bm, int bk,
                                             int kt, int slot) {
    int seg = kt / 12;
    int jl = (kt % 12) * 64;
    int aoff = ((seg == 2) ? 768 : 0) + jl;
    size_t qbase = (seg == 1) ? (size_t)CDIM * CDIM : 0;
    uint32_t abase = sb + slot * 32768;
    uint32_t bbase = abase + 16384;
#pragma unroll
    for (int c = 0; c < 4; c++) {
        int ch = tid + c * 256;               // 0..1023: 128 rows x 8 chunks
        int row = ch >> 3, kc = ch & 7;
        cp_async16(abase + SWZ128(row * 128 + kc * 16),
                   g_Wp + (size_t)(bm + row) * 1536 + aoff + kc * 8);
    }
#pragma unroll
    for (int c = 0; c < 4; c++) {
        int ch = tid + c * 256;               // 0..1023: 64 rows x 16 chunks
        int row = ch >> 4, kc = ch & 15;
        cp_async16(bbase + SWZ256(row * 256 + kc * 16),
                   g_Wq + qbase + (size_t)(jl + row) * CDIM + bk + kc * 8);
    }
}

__global__ __launch_bounds__(256) void compute_B_kernel() {
    extern __shared__ char smem[];
    uint32_t sb = smem_u32(smem);
    int bm = blockIdx.y * 128, bk = blockIdx.x * 128;
    int tid = threadIdx.x;
    int wid = tid >> 5, lane = tid & 31;
    int wm = wid >> 1, wn = wid & 1;

    int l7 = lane & 7, sel = lane >> 3;
    int rsel = (sel & 1) * 8;
    int csel = (sel >> 1) * 16;
    int g1 = (lane >> 3) & 1;
    int g2 = (lane >> 4) * 16;

    float acc[2][8][4];
#pragma unroll
    for (int i = 0; i < 2; i++)
#pragma unroll
        for (int j = 0; j < 8; j++)
#pragma unroll
            for (int v = 0; v < 4; v++) acc[i][j][v] = 0.f;

    cb_load_tile(sb, tid, bm, bk, 0, 0);
    CP_COMMIT();

    for (int kt = 0; kt < 36; kt++) {
        if (kt + 1 < 36) {
            cb_load_tile(sb, tid, bm, bk, kt + 1, (kt + 1) & 1);
            CP_COMMIT();
            CP_WAIT1();
        } else {
            CP_WAIT0();
        }
        __syncthreads();

        uint32_t ab = sb + (kt & 1) * 32768;
        uint32_t bb = ab + 16384;
#pragma unroll
        for (int ks = 0; ks < 4; ks++) {
            uint32_t afrag[2][4];
#pragma unroll
            for (int mt = 0; mt < 2; mt++) {
                int row = wm * 32 + mt * 16 + l7 + rsel;
                ldmx4(afrag[mt], ab + SWZ128(row * 128 + ks * 32 + csel));
            }
#pragma unroll
            for (int ng = 0; ng < 4; ng++) {
                uint32_t bfrag[4];
                int row = ks * 16 + l7 + g1 * 8;
                int colb = wn * 128 + ng * 32 + g2;
                ldmx4t(bfrag, bb + SWZ256(row * 256 + colb));
#pragma unroll
                for (int mt = 0; mt < 2; mt++) {
                    mma16816b(acc[mt][ng * 2 + 0], afrag[mt], bfrag[0], bfrag[1]);
                    mma16816b(acc[mt][ng * 2 + 1], afrag[mt], bfrag[2], bfrag[3]);
                }
            }
        }
        __syncthreads();
    }

    int rq = lane >> 2, cq = (lane & 3) * 2;
#pragma unroll
    for (int mt = 0; mt < 2; mt++) {
#pragma unroll
        for (int n8 = 0; n8 < 8; n8++) {
            float* d = acc[mt][n8];
            int n0 = bm + wm * 32 + mt * 16 + rq;
            int k = bk + wn * 64 + n8 * 8 + cq;
            *(__half2*)(g_Bh + (size_t)n0 * CDIM + k) = __floats2half2_rn(d[0], d[1]);
            *(__half2*)(g_Bh + (size_t)(n0 + 8) * CDIM + k) = __floats2half2_rn(d[2], d[3]);
        }
    }
}

// ---------------------------------------------------------------------------
// 2) x -> fp16 (8 floats -> 16B store per thread)
// ---------------------------------------------------------------------------
__global__ __launch_bounds__(256) void prep_a_kernel(const float* __restrict__ x) {
    size_t i8 = ((size_t)blockIdx.x * 256 + threadIdx.x) * 8;
    if (i8 >= (size_t)BATCH * NTOK * CDIM) return;
    float4 v0 = *(const float4*)(x + i8);
    float4 v1 = *(const float4*)(x + i8 + 4);
    __half2 h[4];
    h[0] = __floats2half2_rn(v0.x, v0.y);
    h[1] = __floats2half2_rn(v0.z, v0.w);
    h[2] = __floats2half2_rn(v1.x, v1.y);
    h[3] = __floats2half2_rn(v1.z, v1.w);
    *(uint4*)(g_Ah + i8) = *(uint4*)h;
}

// ---------------------------------------------------------------------------
// 3) Fused GEMM + pass1. CTA tile 128(M) x 256(N), K-tile 64, 4-stage ring.
//    512 threads, 16 warps as 4m x 4n, warp tile 32x64.
//    Epilogue: Z fp16 -> smem stage -> fused U = T1 * Z -> g_Uh.
// ---------------------------------------------------------------------------
#define GM_NT 12
#define STG_BYTES 49152          /* A 16KB + B 32KB per stage */
#define NSTAGE 4
#define GM_SMEM (NSTAGE * STG_BYTES + 16384)   /* + T1 (16KB) */
#define GM_THREADS 512

__device__ __forceinline__ void gemm_load_tile(uint32_t sb, int tid, int bm, int bn,
                                               int kt, int slot) {
    int koff = kt * 64;
    uint32_t abase = sb + slot * STG_BYTES;
    uint32_t bbase = abase + 16384;
#pragma unroll
    for (int c = 0; c < 2; c++) {
        int ch = tid + c * GM_THREADS;        // 0..1023: 128 rows x 8 chunks
        int row = ch >> 3, kc = ch & 7;
        cp_async16(abase + SWZ128(row * 128 + kc * 16),
                   g_Ah + (size_t)(bm + row) * CDIM + koff + kc * 8);
    }
#pragma unroll
    for (int c = 0; c < 4; c++) {
        int ch = tid + c * GM_THREADS;        // 0..2047: 256 rows x 8 chunks
        int row = ch >> 3, kc = ch & 7;
        cp_async16(bbase + SWZ128(row * 128 + kc * 16),
                   g_Bh + (size_t)(bn + row) * CDIM + koff + kc * 8);
    }
}

__global__ __launch_bounds__(GM_THREADS) void gemm_mma_kernel() {
    extern __shared__ char smem[];
    uint32_t sb = smem_u32(smem);
    uint32_t sbT1 = sb + NSTAGE * STG_BYTES;
    __half* stage1 = (__half*)smem;                             // Z tile 128x264 (67584B)
    __half* stage2 = (__half*)(smem + 128 * STG1_ROWH * 2);     // U tile 128x264 (67584B)
    uint32_t sbS1 = sb;
    int tid = threadIdx.x;
    int wid = tid >> 5, lane = tid & 31;
    int wm = wid >> 2, wn = wid & 3;          // 4m x 4n
    int bm = blockIdx.y * 128;
    int bn = blockIdx.x * 256;
    int b = bm >> 12;                 // batch
    int r0 = (bm >> 6) & 63;          // first spatial row of this tile

    int l7 = lane & 7, sel = lane >> 3;
    int rsel = (sel & 1) * 8;
    int csel = (sel >> 1) * 16;
    int g1 = (lane >> 3) & 1;
    int g2 = (lane >> 4) * 16;

    float acc[2][8][4];
#pragma unroll
    for (int i = 0; i < 2; i++)
#pragma unroll
        for (int j = 0; j < 8; j++)
#pragma unroll
            for (int v = 0; v < 4; v++) acc[i][j][v] = 0.f;

    // prologue: T1 + tile0 in group 0; tiles 1,2 in groups 1,2
#pragma unroll
    for (int c = 0; c < 2; c++) {
        int o = (tid + c * GM_THREADS) * 16;  // 0..16383
        cp_async16(sbT1 + SWZ128(o), (const char*)g_T1h + o);
    }
    gemm_load_tile(sb, tid, bm, bn, 0, 0);
    CP_COMMIT();
    gemm_load_tile(sb, tid, bm, bn, 1, 1);
    CP_COMMIT();
    gemm_load_tile(sb, tid, bm, bn, 2, 2);
    CP_COMMIT();

    for (int kt = 0; kt < GM_NT; kt++) {
        CP_WAIT2();
        __syncthreads();

        if (kt + NSTAGE - 1 < GM_NT)
            gemm_load_tile(sb, tid, bm, bn, kt + NSTAGE - 1, (kt + NSTAGE - 1) & (NSTAGE - 1));
        CP_COMMIT();

        uint32_t ab = sb + (kt & (NSTAGE - 1)) * STG_BYTES;
        uint32_t bb = ab + 16384;
#pragma unroll
        for (int ks = 0; ks < 4; ks++) {
            uint32_t afrag[2][4];
#pragma unroll
            for (int mt = 0; mt < 2; mt++) {
                int row = wm * 32 + mt * 16 + l7 + rsel;
                ldmx4(afrag[mt], ab + SWZ128(row * 128 + ks * 32 + csel));
            }
#pragma unroll
            for (int nt = 0; nt < 4; nt++) {
                uint32_t bfrag[4];
                int row = wn * 64 + nt * 16 + l7 + rsel;
                ldmx4(bfrag, bb + SWZ128(row * 128 + ks * 32 + csel));
#pragma unroll
                for (int mt = 0; mt < 2; mt++) {
                    mma16816h(acc[mt][nt * 2 + 0], afrag[mt], bfrag[0], bfrag[2]);
                    mma16816h(acc[mt][nt * 2 + 1], afrag[mt], bfrag[1], bfrag[3]);
                }
            }
        }
    }

    // ---- stage Z (fp16) into stage1 ----
    CP_WAIT0();
    __syncthreads();
    int rq = lane >> 2, cq = (lane & 3) * 2;
#pragma unroll
    for (int mt = 0; mt < 2; mt++) {
#pragma unroll
        for (int n8 = 0; n8 < 8; n8++) {
            float* d = acc[mt][n8];
            int row = wm * 32 + mt * 16 + rq;
            int c = wn * 64 + n8 * 8 + cq;
            *(__half2*)&stage1[row * STG1_ROWH + c] = __floats2half2_rn(d[0], d[1]);
            *(__half2*)&stage1[(row + 8) * STG1_ROWH + c] = __floats2half2_rn(d[2], d[3]);
        }
    }
    __syncthreads();

    // ---- fused pass1: per half h (spatial row r0+h): U[128i x 256ch] = T1 * Z_h ----
#pragma unroll
    for (int h = 0; h < 2; h++) {
        float uacc[2][8][4];
#pragma unroll
        for (int i = 0; i < 2; i++)
#pragma unroll
            for (int j = 0; j < 8; j++)
#pragma unroll
                for (int v = 0; v < 4; v++) uacc[i][j][v] = 0.f;

#pragma unroll
        for (int ks = 0; ks < 4; ks++) {
            uint32_t afrag[2][4];
#pragma unroll
            for (int mt = 0; mt < 2; mt++) {
                int row = wm * 32 + mt * 16 + l7 + rsel;
                ldmx4(afrag[mt], sbT1 + SWZ128(row * 128 + ks * 32 + csel));
            }
#pragma unroll
            for (int ng = 0; ng < 4; ng++) {
                uint32_t bfrag[4];
                int srow = h * 64 + ks * 16 + l7 + g1 * 8;
                int colb = wn * 128 + ng * 32 + g2;
                ldmx4t(bfrag, sbS1 + srow * (STG1_ROWH * 2) + colb);
#pragma unroll
                for (int mt = 0; mt < 2; mt++) {
                    mma16816h(uacc[mt][ng * 2 + 0], afrag[mt], bfrag[0], bfrag[1]);
                    mma16816h(uacc[mt][ng * 2 + 1], afrag[mt], bfrag[2], bfrag[3]);
                }
            }
        }

        if (h == 1) __syncthreads();      // prior stage2 store-read complete
#pragma unroll
        for (int mt = 0; mt < 2; mt++) {
#pragma unroll
            for (int n8 = 0; n8 < 8; n8++) {
                float* d = uacc[mt][n8];
                int i0 = wm * 32 + mt * 16 + rq;
                int chl = wn * 64 + n8 * 8 + cq;
                *(__half2*)&stage2[i0 * STG1_ROWH + chl] = __floats2half2_rn(d[0], d[1]);
                *(__half2*)&stage2[(i0 + 8) * STG1_ROWH + chl] = __floats2half2_rn(d[2], d[3]);
            }
        }
        __syncthreads();
        int r = r0 + h;
#pragma unroll
        for (int it = 0; it < 8; it++) {
            int idx = tid + it * GM_THREADS;      // 0..4095: 128 rows x 32 chunks
            int row = idx >> 5, ck = idx & 31;
            int q = row & 63;
            int kk = (row < 64) ? r : 64 + r;
            uint4 v = *(uint4*)&stage2[row * STG1_ROWH + ck * 8];
            *(uint4*)(g_Uh + ((size_t)(b * 64 + q) * 128 + kk) * CDIM + bn + ck * 8) = v;
        }
    }
}

// ---------------------------------------------------------------------------
// 4) Pass 2 (fp16 mma): per (b, q): out[64p x ch] = T2 * U + bias,
//    looping over all 6 channel tiles with double-buffered B.
// ---------------------------------------------------------------------------
#define P2_SMEM (16384 + 2 * 32768)

__global__ __launch_bounds__(256) void pass2_kernel(
    const float* __restrict__ bias, float* __restrict__ out)
{
    extern __shared__ char smem[];
    uint32_t sb = smem_u32(smem);
    uint32_t sbA = sb;
    int b = blockIdx.y, q = blockIdx.x;
    int tid = threadIdx.x;
    int wid = tid >> 5, lane = tid & 31;
    int wm = wid >> 2, wn = wid & 3;

    const __half* usrc = g_Uh + (size_t)(b * 64 + q) * 128 * CDIM;

    // prologue: A (T2) + B tile 0 -> group 0
#pragma unroll
    for (int c = 0; c < 4; c++) {
        int idx = tid + c * 256;
        int p = idx >> 4, ck = idx & 15;
        cp_async16(sbA + SWZ256(p * 256 + ck * 16), g_T2h + p * 128 + ck * 8);
    }
#pragma unroll
    for (int c = 0; c < 8; c++) {
        int idx = tid + c * 256;
        int k = idx >> 4, ck = idx & 15;
        cp_async16(sb + 16384 + SWZ256(k * 256 + ck * 16),
                   usrc + (size_t)k * CDIM + 0 + ck * 8);
    }
    CP_COMMIT();

    int l7 = lane & 7, sel = lane >> 3;
    int rsel = (sel & 1) * 8;
    int csel = (sel >> 1) * 16;
    int g1 = (lane >> 3) & 1;
    int g2 = (lane >> 4) * 16;

    for (int cht = 0; cht < 6; cht++) {
        __syncthreads();
        if (cht + 1 < 6) {
            uint32_t bbuf = sb + 16384 + ((cht + 1) & 1) * 32768;
            int c1 = (cht + 1) * 128;
#pragma unroll
            for (int c = 0; c < 8; c++) {
                int idx = tid + c * 256;
                int k = idx >> 4, ck = idx & 15;
                cp_async16(bbuf + SWZ256(k * 256 + ck * 16),
                           usrc + (size_t)k * CDIM + c1 + ck * 8);
            }
            CP_COMMIT();
            CP_WAIT1();
        } else {
            CP_WAIT0();
        }
        __syncthreads();

        uint32_t sbB = sb + 16384 + (cht & 1) * 32768;
        int c0 = cht * 128;

        float acc[2][4][4];
#pragma unroll
        for (int i = 0; i < 2; i++)
#pragma unroll
            for (int j = 0; j < 4; j++)
#pragma unroll
                for (int v = 0; v < 4; v++) acc[i][j][v] = 0.f;

#pragma unroll
        for (int ks = 0; ks < 8; ks++) {
            uint32_t afrag[2][4];
#pragma unroll
            for (int mt = 0; mt < 2; mt++) {
                int row = wm * 32 + mt * 16 + l7 + rsel;
                ldmx4(afrag[mt], sbA + SWZ256(row * 256 + ks * 32 + csel));
            }
#pragma unroll
            for (int ng = 0; ng < 2; ng++) {
                uint32_t bfrag[4];
                int row = ks * 16 + l7 + g1 * 8;
                int colb = wn * 64 + ng * 32 + g2;
                ldmx4t(bfrag, sbB + SWZ256(row * 256 + colb));
#pragma unroll
                for (int mt = 0; mt < 2; mt++) {
                    mma16816h(acc[mt][ng * 2 + 0], afrag[mt], bfrag[0], bfrag[1]);
                    mma16816h(acc[mt][ng * 2 + 1], afrag[mt], bfrag[2], bfrag[3]);
                }
            }
        }

        int rq = lane >> 2, cq = (lane & 3) * 2;
#pragma unroll
        for (int mt = 0; mt < 2; mt++) {
            int pbase = wm * 32 + mt * 16;
#pragma unroll
            for (int n8 = 0; n8 < 4; n8++) {
                float* d = acc[mt][n8];
                int ch = c0 + wn * 32 + n8 * 8 + cq;
                float2 bv = *(const float2*)(bias + ch);
                int p0 = pbase + rq, p1 = pbase + rq + 8;
                float* o0 = out + ((size_t)b * NTOK + p0 * 64 + q) * CDIM + ch;
                float* o1 = out + ((size_t)b * NTOK + p1 * 64 + q) * CDIM + ch;
                *(float2*)o0 = make_float2(d[0] + bv.x, d[1] + bv.y);
                *(float2*)o1 = make_float2(d[2] + bv.x, d[3] + bv.y);
            }
        }
    }
}

// ---------------------------------------------------------------------------
// launch
// ---------------------------------------------------------------------------
extern "C" void kernel_launch(void* const* d_in, const int* in_sizes, int n_in,
                              void* d_out, int out_size)
{
    const float* x      = (const float*)d_in[0];   // [8,4096,768]
    const float* qkv_w  = (const float*)d_in[1];   // [2304,768]
    const float* proj_w = (const float*)d_in[2];   // [768,768]
    const float* proj_b = (const float*)d_in[3];   // [768]
    float* out = (float*)d_out;

    cudaFuncSetAttribute(gemm_mma_kernel,  cudaFuncAttributeMaxDynamicSharedMemorySize, GM_SMEM);
    cudaFuncSetAttribute(pass2_kernel,     cudaFuncAttributeMaxDynamicSharedMemorySize, P2_SMEM);
    cudaFuncSetAttribute(compute_B_kernel, cudaFuncAttributeMaxDynamicSharedMemorySize, CB_SMEM);

    init_tables_kernel<<<1, 256>>>();
    prep_w_kernel<<<(CDIM * CDIM + 255) / 256, 256>>>(qkv_w, proj_w);
    compute_B_kernel<<<dim3(CDIM / 128, CDIM / 128), 256, CB_SMEM>>>();
    prep_a_kernel<<<(int)(((size_t)BATCH * NTOK * CDIM / 8 + 255) / 256), 256>>>(x);
    gemm_mma_kernel<<<dim3(CDIM / 256, (BATCH * NTOK) / 128), GM_THREADS, GM_SMEM>>>();
    pass2_kernel<<<dim3(64, BATCH), 256, P2_SMEM>>>(proj_b, out);
}

// round 15
// speedup vs baseline: 1.5430x; 1.0578x over previous
#include <cuda_runtime.h>
#include <cuda_bf16.h>
#include <cuda_fp16.h>
#include <cstdint>
#include <math.h>

// Problem constants
#define BATCH 8
#define NTOK  4096
#define CDIM  768

// ---------------------------------------------------------------------------
// device scratch (no runtime allocation allowed)
// ---------------------------------------------------------------------------
__device__ __align__(16) __half g_Ah[(size_t)BATCH * NTOK * CDIM];   // [32768][768] fp16 x
__device__ __align__(16) __half g_Bh[(size_t)CDIM * CDIM];           // [768 n][768 k] fp16 M^T
__device__ __align__(16) __half g_Uh[(size_t)BATCH * 64 * 128 * CDIM]; // [(b,q,k)][768] fp16 U
__device__ __align__(16) __half g_T1h[128 * 64];                     // [i][s] i<64: cos(i*s), else sin
__device__ __align__(16) __half g_T2h[64 * 128];                     // [p][k] k<64: cos(p*k), else -sin
__device__ __align__(16) __nv_bfloat16 g_Wp[(size_t)CDIM * 2 * CDIM];   // [768 n][1536]: proj hi|lo
__device__ __align__(16) __nv_bfloat16 g_Wq[(size_t)2 * CDIM * CDIM];   // [chunk][768 j][768 k]: qkv-v hi,lo

// ---------------------------------------------------------------------------
// PTX helpers (baseline compute_103-safe)
// ---------------------------------------------------------------------------
__device__ __forceinline__ uint32_t smem_u32(const void* p) {
    uint32_t a;
    asm("{ .reg .u64 t; cvta.to.shared.u64 t, %1; cvt.u32.u64 %0, t; }" : "=r"(a) : "l"(p));
    return a;
}
__device__ __forceinline__ void cp_async16(uint32_t sa, const void* ga) {
    asm volatile("cp.async.cg.shared.global [%0], [%1], 16;" :: "r"(sa), "l"(ga));
}
#define CP_COMMIT() asm volatile("cp.async.commit_group;" ::: "memory")
#define CP_WAIT1()  asm volatile("cp.async.wait_group 1;" ::: "memory")
#define CP_WAIT0()  asm volatile("cp.async.wait_group 0;" ::: "memory")
#define SWZ128(o)   ((o) ^ (((o) >> 3) & 0x70))
#define SWZ256(o)   ((o) ^ (((o) >> 4) & 0x70))

__device__ __forceinline__ void ldmx4(uint32_t* r, uint32_t addr) {
    asm volatile("ldmatrix.sync.aligned.m8n8.x4.shared.b16 {%0,%1,%2,%3}, [%4];"
                 : "=r"(r[0]), "=r"(r[1]), "=r"(r[2]), "=r"(r[3]) : "r"(addr));
}
__device__ __forceinline__ void ldmx4t(uint32_t* r, uint32_t addr) {
    asm volatile("ldmatrix.sync.aligned.m8n8.x4.trans.shared.b16 {%0,%1,%2,%3}, [%4];"
                 : "=r"(r[0]), "=r"(r[1]), "=r"(r[2]), "=r"(r[3]) : "r"(addr));
}
__device__ __forceinline__ void mma16816h(float* d, const uint32_t* a, uint32_t b0, uint32_t b1) {
    asm volatile("mma.sync.aligned.m16n8k16.row.col.f32.f16.f16.f32 "
                 "{%0,%1,%2,%3},{%4,%5,%6,%7},{%8,%9},{%0,%1,%2,%3};"
                 : "+f"(d[0]), "+f"(d[1]), "+f"(d[2]), "+f"(d[3])
                 : "r"(a[0]), "r"(a[1]), "r"(a[2]), "r"(a[3]), "r"(b0), "r"(b1));
}
__device__ __forceinline__ void mma16816b(float* d, const uint32_t* a, uint32_t b0, uint32_t b1) {
    asm volatile("mma.sync.aligned.m16n8k16.row.col.f32.bf16.bf16.f32 "
                 "{%0,%1,%2,%3},{%4,%5,%6,%7},{%8,%9},{%0,%1,%2,%3};"
                 : "+f"(d[0]), "+f"(d[1]), "+f"(d[2]), "+f"(d[3])
                 : "r"(a[0]), "r"(a[1]), "r"(a[2]), "r"(a[3]), "r"(b0), "r"(b1));
}

#define STG_ROWH 136   /* stage row stride in halves (272B): conflict-free, 16B-aligned */

// ---------------------------------------------------------------------------
// 0) merged setup: weight hi/lo split (blocks 0..2303) + twiddle tables (last)
// ---------------------------------------------------------------------------
__global__ __launch_bounds__(256) void setup_kernel(
    const float* __restrict__ qkv_w, const float* __restrict__ proj_w)
{
    if (blockIdx.x < 2304) {
        int i = blockIdx.x * 256 + threadIdx.x;
        if (i >= CDIM * CDIM) return;
        int r = i / CDIM, c = i % CDIM;
        {
            float v = proj_w[i];
            __nv_bfloat16 h = __float2bfloat16(v);
            g_Wp[(size_t)r * 1536 + c] = h;
            g_Wp[(size_t)r * 1536 + 768 + c] = __float2bfloat16(v - __bfloat162float(h));
        }
        {
            float v = qkv_w[(size_t)(2 * CDIM + r) * CDIM + c];
            __nv_bfloat16 h = __float2bfloat16(v);
            g_Wq[i] = h;
            g_Wq[(size_t)CDIM * CDIM + i] = __float2bfloat16(v - __bfloat162float(h));
        }
    } else {
        __shared__ float cb[64], sb_[64];
        int tid = threadIdx.x;
        const double TWO_PI = 6.283185307179586476925286766559;
        if (tid < 64) {
            double ang = TWO_PI * (double)tid / 64.0;
            cb[tid] = (float)cos(ang);
            sb_[tid] = (float)sin(ang);
        }
        __syncthreads();
        for (int i = tid; i < 128 * 64; i += 256) {
            int row = i >> 6, s = i & 63;
            int idx = ((row & 63) * s) & 63;
            g_T1h[i] = __float2half_rn((row < 64) ? cb[idx] : sb_[idx]);
        }
        for (int i = tid; i < 64 * 128; i += 256) {
            int p = i >> 7, k = i & 127;
            int idx = (p * (k & 63)) & 63;
            g_T2h[i] = __float2half_rn((k < 64) ? cb[idx] : -sb_[idx]);
        }
    }
}

// ---------------------------------------------------------------------------
// 1) B build via bf16 split 3-term mma GEMM:
//    g_Bh[n][k] = fp16( sum_j proj_w[n][j] * qkv_w[2C+j][k] )
//    CTA 128(n) x 128(k), K logical 2304, 36 K-tiles, 2-stage ring.
// ---------------------------------------------------------------------------
#define CB_SMEM (2 * 32768)

__device__ __forceinline__ void cb_load_tile(uint32_t sb, int tid, int bm, int bk,
                                             int kt, int slot) {
    int seg = kt / 12;
    int jl = (kt % 12) * 64;
    int aoff = ((seg == 2) ? 768 : 0) + jl;
    size_t qbase = (seg == 1) ? (size_t)CDIM * CDIM : 0;
    uint32_t abase = sb + slot * 32768;
    uint32_t bbase = abase + 16384;
#pragma unroll
    for (int c = 0; c < 4; c++) {
        int ch = tid + c * 256;
        int row = ch >> 3, kc = ch & 7;
        cp_async16(abase + SWZ128(row * 128 + kc * 16),
                   g_Wp + (size_t)(bm + row) * 1536 + aoff + kc * 8);
    }
#pragma unroll
    for (int c = 0; c < 4; c++) {
        int ch = tid + c * 256;
        int row = ch >> 4, kc = ch & 15;
        cp_async16(bbase + SWZ256(row * 256 + kc * 16),
                   g_Wq + qbase + (size_t)(jl + row) * CDIM + bk + kc * 8);
    }
}

__global__ __launch_bounds__(256) void compute_B_kernel() {
    extern __shared__ char smem[];
    uint32_t sb = smem_u32(smem);
    int bm = blockIdx.y * 128, bk = blockIdx.x * 128;
    int tid = threadIdx.x;
    int wid = tid >> 5, lane = tid & 31;
    int wm = wid >> 1, wn = wid & 1;

    int l7 = lane & 7, sel = lane >> 3;
    int rsel = (sel & 1) * 8;
    int csel = (sel >> 1) * 16;
    int g1 = (lane >> 3) & 1;
    int g2 = (lane >> 4) * 16;

    float acc[2][8][4];
#pragma unroll
    for (int i = 0; i < 2; i++)
#pragma unroll
        for (int j = 0; j < 8; j++)
#pragma unroll
            for (int v = 0; v < 4; v++) acc[i][j][v] = 0.f;

    cb_load_tile(sb, tid, bm, bk, 0, 0);
    CP_COMMIT();

    for (int kt = 0; kt < 36; kt++) {
        if (kt + 1 < 36) {
            cb_load_tile(sb, tid, bm, bk, kt + 1, (kt + 1) & 1);
            CP_COMMIT();
            CP_WAIT1();
        } else {
            CP_WAIT0();
        }
        __syncthreads();

        uint32_t ab = sb + (kt & 1) * 32768;
        uint32_t bb = ab + 16384;
#pragma unroll
        for (int ks = 0; ks < 4; ks++) {
            uint32_t afrag[2][4];
#pragma unroll
            for (int mt = 0; mt < 2; mt++) {
                int row = wm * 32 + mt * 16 + l7 + rsel;
                ldmx4(afrag[mt], ab + SWZ128(row * 128 + ks * 32 + csel));
            }
#pragma unroll
            for (int ng = 0; ng < 4; ng++) {
                uint32_t bfrag[4];
                int row = ks * 16 + l7 + g1 * 8;
                int colb = wn * 128 + ng * 32 + g2;
                ldmx4t(bfrag, bb + SWZ256(row * 256 + colb));
#pragma unroll
                for (int mt = 0; mt < 2; mt++) {
                    mma16816b(acc[mt][ng * 2 + 0], afrag[mt], bfrag[0], bfrag[1]);
                    mma16816b(acc[mt][ng * 2 + 1], afrag[mt], bfrag[2], bfrag[3]);
                }
            }
        }
        __syncthreads();
    }

    int rq = lane >> 2, cq = (lane & 3) * 2;
#pragma unroll
    for (int mt = 0; mt < 2; mt++) {
#pragma unroll
        for (int n8 = 0; n8 < 8; n8++) {
            float* d = acc[mt][n8];
            int n0 = bm + wm * 32 + mt * 16 + rq;
            int k = bk + wn * 64 + n8 * 8 + cq;
            *(__half2*)(g_Bh + (size_t)n0 * CDIM + k) = __floats2half2_rn(d[0], d[1]);
            *(__half2*)(g_Bh + (size_t)(n0 + 8) * CDIM + k) = __floats2half2_rn(d[2], d[3]);
        }
    }
}

// ---------------------------------------------------------------------------
// 2) x -> fp16 (8 floats -> 16B store per thread)
// ---------------------------------------------------------------------------
__global__ __launch_bounds__(256) void prep_a_kernel(const float* __restrict__ x) {
    size_t i8 = ((size_t)blockIdx.x * 256 + threadIdx.x) * 8;
    if (i8 >= (size_t)BATCH * NTOK * CDIM) return;
    float4 v0 = *(const float4*)(x + i8);
    float4 v1 = *(const float4*)(x + i8 + 4);
    __half2 h[4];
    h[0] = __floats2half2_rn(v0.x, v0.y);
    h[1] = __floats2half2_rn(v0.z, v0.w);
    h[2] = __floats2half2_rn(v1.x, v1.y);
    h[3] = __floats2half2_rn(v1.z, v1.w);
    *(uint4*)(g_Ah + i8) = *(uint4*)h;
}

// ---------------------------------------------------------------------------
// 3) Fused GEMM + pass1. CTA tile 128(M) x 128(N), K-tile 64, 3-stage ring.
//    256 threads, 8 warps as 4m x 2n, warp tile 32x64. Target 2 CTAs/SM.
//    Epilogue: Z fp16 -> smem stage -> fused U = T1 * Z -> g_Uh.
// ---------------------------------------------------------------------------
#define GM_NT 12
#define STG_BYTES 32768          /* A 16KB + B 16KB per stage */
#define NSTAGE 3
#define GM_SMEM (NSTAGE * STG_BYTES + 16384)   /* + T1 (16KB) = 114688 */

__device__ __forceinline__ void gemm_load_tile(uint32_t sb, int tid, int bm, int bn,
                                               int kt, int slot) {
    int koff = kt * 64;
    uint32_t abase = sb + slot * STG_BYTES;
    uint32_t bbase = abase + 16384;
#pragma unroll
    for (int c = 0; c < 4; c++) {
        int ch = tid + c * 256;               // 0..1023: 128 rows x 8 chunks
        int row = ch >> 3, kc = ch & 7;
        cp_async16(abase + SWZ128(row * 128 + kc * 16),
                   g_Ah + (size_t)(bm + row) * CDIM + koff + kc * 8);
    }
#pragma unroll
    for (int c = 0; c < 4; c++) {
        int ch = tid + c * 256;
        int row = ch >> 3, kc = ch & 7;
        cp_async16(bbase + SWZ128(row * 128 + kc * 16),
                   g_Bh + (size_t)(bn + row) * CDIM + koff + kc * 8);
    }
}

__global__ __launch_bounds__(256, 2) void gemm_mma_kernel() {
    extern __shared__ char smem[];
    uint32_t sb = smem_u32(smem);
    uint32_t sbT1 = sb + NSTAGE * STG_BYTES;
    __half* stage1 = (__half*)smem;                            // Z tile (34816B)
    __half* stage2 = (__half*)(smem + 128 * STG_ROWH * 2);     // U tile (34816B)
    uint32_t sbS1 = sb;
    int tid = threadIdx.x;
    int wid = tid >> 5, lane = tid & 31;
    int wm = wid >> 1, wn = wid & 1;
    int bm = blockIdx.y * 128;
    int bn = blockIdx.x * 128;
    int b = bm >> 12;                 // batch
    int r0 = (bm >> 6) & 63;          // first spatial row of this tile

    int l7 = lane & 7, sel = lane >> 3;
    int rsel = (sel & 1) * 8;
    int csel = (sel >> 1) * 16;
    int g1 = (lane >> 3) & 1;
    int g2 = (lane >> 4) * 16;

    float acc[2][8][4];
#pragma unroll
    for (int i = 0; i < 2; i++)
#pragma unroll
        for (int j = 0; j < 8; j++)
#pragma unroll
            for (int v = 0; v < 4; v++) acc[i][j][v] = 0.f;

    // prologue: T1 + tile0 in group 0; tile1 in group 1
#pragma unroll
    for (int c = 0; c < 4; c++) {
        int o = (tid + c * 256) * 16;       // 0..16383
        cp_async16(sbT1 + SWZ128(o), (const char*)g_T1h + o);
    }
    gemm_load_tile(sb, tid, bm, bn, 0, 0);
    CP_COMMIT();
    gemm_load_tile(sb, tid, bm, bn, 1, 1);
    CP_COMMIT();

    for (int kt = 0; kt < GM_NT; kt++) {
        CP_WAIT1();                // tile kt resident (<=1 newer group pending)
        __syncthreads();           // prior compute on slot (kt+2)%3 done

        if (kt + NSTAGE - 1 < GM_NT)
            gemm_load_tile(sb, tid, bm, bn, kt + NSTAGE - 1, (kt + NSTAGE - 1) % NSTAGE);
        CP_COMMIT();               // unconditional: keeps group counts aligned

        uint32_t ab = sb + (kt % NSTAGE) * STG_BYTES;
        uint32_t bb = ab + 16384;
#pragma unroll
        for (int ks = 0; ks < 4; ks++) {
            uint32_t afrag[2][4];
#pragma unroll
            for (int mt = 0; mt < 2; mt++) {
                int row = wm * 32 + mt * 16 + l7 + rsel;
                ldmx4(afrag[mt], ab + SWZ128(row * 128 + ks * 32 + csel));
            }
#pragma unroll
            for (int nt = 0; nt < 4; nt++) {
                uint32_t bfrag[4];
                int row = wn * 64 + nt * 16 + l7 + rsel;
                ldmx4(bfrag, bb + SWZ128(row * 128 + ks * 32 + csel));
#pragma unroll
                for (int mt = 0; mt < 2; mt++) {
                    mma16816h(acc[mt][nt * 2 + 0], afrag[mt], bfrag[0], bfrag[2]);
                    mma16816h(acc[mt][nt * 2 + 1], afrag[mt], bfrag[1], bfrag[3]);
                }
            }
        }
    }

    // ---- stage Z (fp16) into stage1 ----
    CP_WAIT0();
    __syncthreads();
    int rq = lane >> 2, cq = (lane & 3) * 2;
#pragma unroll
    for (int mt = 0; mt < 2; mt++) {
#pragma unroll
        for (int n8 = 0; n8 < 8; n8++) {
            float* d = acc[mt][n8];
            int row = wm * 32 + mt * 16 + rq;
            int c = wn * 64 + n8 * 8 + cq;
            *(__half2*)&stage1[row * STG_ROWH + c] = __floats2half2_rn(d[0], d[1]);
            *(__half2*)&stage1[(row + 8) * STG_ROWH + c] = __floats2half2_rn(d[2], d[3]);
        }
    }
    __syncthreads();

    // ---- fused pass1: per half h (spatial row r0+h): U[128i x 128ch] = T1 * Z_h ----
#pragma unroll
    for (int h = 0; h < 2; h++) {
        float uacc[2][8][4];
#pragma unroll
        for (int i = 0; i < 2; i++)
#pragma unroll
            for (int j = 0; j < 8; j++)
#pragma unroll
                for (int v = 0; v < 4; v++) uacc[i][j][v] = 0.f;

#pragma unroll
        for (int ks = 0; ks < 4; ks++) {
            uint32_t afrag[2][4];
#pragma unroll
            for (int mt = 0; mt < 2; mt++) {
                int row = wm * 32 + mt * 16 + l7 + rsel;
                ldmx4(afrag[mt], sbT1 + SWZ128(row * 128 + ks * 32 + csel));
            }
#pragma unroll
            for (int ng = 0; ng < 4; ng++) {
                uint32_t bfrag[4];
                int srow = h * 64 + ks * 16 + l7 + g1 * 8;
                int colb = wn * 128 + ng * 32 + g2;
                ldmx4t(bfrag, sbS1 + srow * (STG_ROWH * 2) + colb);
#pragma unroll
                for (int mt = 0; mt < 2; mt++) {
                    mma16816h(uacc[mt][ng * 2 + 0], afrag[mt], bfrag[0], bfrag[1]);
                    mma16816h(uacc[mt][ng * 2 + 1], afrag[mt], bfrag[2], bfrag[3]);
                }
            }
        }

        if (h == 1) __syncthreads();      // prior stage2 store-read complete
#pragma unroll
        for (int mt = 0; mt < 2; mt++) {
#pragma unroll
            for (int n8 = 0; n8 < 8; n8++) {
                float* d = uacc[mt][n8];
                int i0 = wm * 32 + mt * 16 + rq;
                int chl = wn * 64 + n8 * 8 + cq;
                *(__half2*)&stage2[i0 * STG_ROWH + chl] = __floats2half2_rn(d[0], d[1]);
                *(__half2*)&stage2[(i0 + 8) * STG_ROWH + chl] = __floats2half2_rn(d[2], d[3]);
            }
        }
        __syncthreads();
        int r = r0 + h;
#pragma unroll
        for (int it = 0; it < 8; it++) {
            int idx = tid + it * 256;             // 0..2047: 128 rows x 16 chunks
            int row = idx >> 4, ck = idx & 15;
            int q = row & 63;
            int kk = (row < 64) ? r : 64 + r;
            uint4 v = *(uint4*)&stage2[row * STG_ROWH + ck * 8];
            *(uint4*)(g_Uh + ((size_t)(b * 64 + q) * 128 + kk) * CDIM + bn + ck * 8) = v;
        }
    }
}

// ---------------------------------------------------------------------------
// 4) Pass 2, single-shot: grid (6 cht, 64 q, 8 b). Each CTA:
//    out[64p x 128ch] = T2 * U(b,q) + bias for one 128-ch slice.
// ---------------------------------------------------------------------------
#define P2_SMEM (16384 + 32768)

__global__ __launch_bounds__(256) void pass2_kernel(
    const float* __restrict__ bias, float* __restrict__ out)
{
    extern __shared__ char smem[];
    uint32_t sb = smem_u32(smem);
    uint32_t sbA = sb, sbB = sb + 16384;
    int cht = blockIdx.x, q = blockIdx.y, b = blockIdx.z;
    int c0 = cht * 128;
    int tid = threadIdx.x;
    int wid = tid >> 5, lane = tid & 31;
    int wm = wid >> 2, wn = wid & 3;

    const __half* usrc = g_Uh + (size_t)(b * 64 + q) * 128 * CDIM;

#pragma unroll
    for (int c = 0; c < 4; c++) {
        int idx = tid + c * 256;
        int p = idx >> 4, ck = idx & 15;
        cp_async16(sbA + SWZ256(p * 256 + ck * 16), g_T2h + p * 128 + ck * 8);
    }
#pragma unroll
    for (int c = 0; c < 8; c++) {
        int idx = tid + c * 256;
        int k = idx >> 4, ck = idx & 15;
        cp_async16(sbB + SWZ256(k * 256 + ck * 16),
                   usrc + (size_t)k * CDIM + c0 + ck * 8);
    }
    CP_COMMIT();
    CP_WAIT0();
    __syncthreads();

    int l7 = lane & 7, sel = lane >> 3;
    int rsel = (sel & 1) * 8;
    int csel = (sel >> 1) * 16;
    int g1 = (lane >> 3) & 1;
    int g2 = (lane >> 4) * 16;

    float acc[2][4][4];
#pragma unroll
    for (int i = 0; i < 2; i++)
#pragma unroll
        for (int j = 0; j < 4; j++)
#pragma unroll
            for (int v = 0; v < 4; v++) acc[i][j][v] = 0.f;

#pragma unroll
    for (int ks = 0; ks < 8; ks++) {
        uint32_t afrag[2][4];
#pragma unroll
        for (int mt = 0; mt < 2; mt++) {
            int row = wm * 32 + mt * 16 + l7 + rsel;
            ldmx4(afrag[mt], sbA + SWZ256(row * 256 + ks * 32 + csel));
        }
#pragma unroll
        for (int ng = 0; ng < 2; ng++) {
            uint32_t bfrag[4];
            int row = ks * 16 + l7 + g1 * 8;
            int colb = wn * 64 + ng * 32 + g2;
            ldmx4t(bfrag, sbB + SWZ256(row * 256 + colb));
#pragma unroll
            for (int mt = 0; mt < 2; mt++) {
                mma16816h(acc[mt][ng * 2 + 0], afrag[mt], bfrag[0], bfrag[1]);
                mma16816h(acc[mt][ng * 2 + 1], afrag[mt], bfrag[2], bfrag[3]);
            }
        }
    }

    int rq = lane >> 2, cq = (lane & 3) * 2;
#pragma unroll
    for (int mt = 0; mt < 2; mt++) {
        int pbase = wm * 32 + mt * 16;
#pragma unroll
        for (int n8 = 0; n8 < 4; n8++) {
            float* d = acc[mt][n8];
            int ch = c0 + wn * 32 + n8 * 8 + cq;
            float2 bv = *(const float2*)(bias + ch);
            int p0 = pbase + rq, p1 = pbase + rq + 8;
            float* o0 = out + ((size_t)b * NTOK + p0 * 64 + q) * CDIM + ch;
            float* o1 = out + ((size_t)b * NTOK + p1 * 64 + q) * CDIM + ch;
            *(float2*)o0 = make_float2(d[0] + bv.x, d[1] + bv.y);
            *(float2*)o1 = make_float2(d[2] + bv.x, d[3] + bv.y);
        }
    }
}

// ---------------------------------------------------------------------------
// launch
// ---------------------------------------------------------------------------
extern "C" void kernel_launch(void* const* d_in, const int* in_sizes, int n_in,
                              void* d_out, int out_size)
{
    const float* x      = (const float*)d_in[0];   // [8,4096,768]
    const float* qkv_w  = (const float*)d_in[1];   // [2304,768]
    const float* proj_w = (const float*)d_in[2];   // [768,768]
    const float* proj_b = (const float*)d_in[3];   // [768]
    float* out = (float*)d_out;

    cudaFuncSetAttribute(gemm_mma_kernel,  cudaFuncAttributeMaxDynamicSharedMemorySize, GM_SMEM);
    cudaFuncSetAttribute(pass2_kernel,     cudaFuncAttributeMaxDynamicSharedMemorySize, P2_SMEM);
    cudaFuncSetAttribute(compute_B_kernel, cudaFuncAttributeMaxDynamicSharedMemorySize, CB_SMEM);

    setup_kernel<<<2305, 256>>>(qkv_w, proj_w);
    compute_B_kernel<<<dim3(CDIM / 128, CDIM / 128), 256, CB_SMEM>>>();
    prep_a_kernel<<<(int)(((size_t)BATCH * NTOK * CDIM / 8 + 255) / 256), 256>>>(x);
    gemm_mma_kernel<<<dim3(CDIM / 128, (BATCH * NTOK) / 128), 256, GM_SMEM>>>();
    pass2_kernel<<<dim3(6, 64, BATCH), 256, P2_SMEM>>>(proj_b, out);
}

// round 17
// speedup vs baseline: 1.6440x; 1.0655x over previous
#include <cuda_runtime.h>
#include <cuda_bf16.h>
#include <cuda_fp16.h>
#include <cstdint>
#include <math.h>

// Problem constants
#define BATCH 8
#define NTOK  4096
#define CDIM  768

// ---------------------------------------------------------------------------
// device scratch (no runtime allocation allowed)
// ---------------------------------------------------------------------------
__device__ __align__(16) __half g_Ah[(size_t)BATCH * NTOK * CDIM];   // [32768][768] fp16 x
__device__ __align__(16) __half g_Bh[(size_t)CDIM * CDIM];           // [768 n][768 k] fp16 M^T
__device__ __align__(16) __half g_Uh[(size_t)BATCH * 64 * 128 * CDIM]; // [(b,q,k)][768] fp16 U
__device__ __align__(16) __half g_T1h[128 * 64];                     // [i][s] i<64: cos(i*s), else sin
__device__ __align__(16) __half g_T2h[64 * 128];                     // [p][k] k<64: cos(p*k), else -sin
__device__ __align__(16) __nv_bfloat16 g_Wp[(size_t)CDIM * 2 * CDIM];   // [768 n][1536]: proj hi|lo
__device__ __align__(16) __nv_bfloat16 g_Wq[(size_t)2 * CDIM * CDIM];   // [chunk][768 j][768 k]: qkv-v hi,lo

// ---------------------------------------------------------------------------
// PTX helpers (baseline compute_103-safe)
// ---------------------------------------------------------------------------
__device__ __forceinline__ uint32_t smem_u32(const void* p) {
    uint32_t a;
    asm("{ .reg .u64 t; cvta.to.shared.u64 t, %1; cvt.u32.u64 %0, t; }" : "=r"(a) : "l"(p));
    return a;
}
__device__ __forceinline__ void cp_async16(uint32_t sa, const void* ga) {
    asm volatile("cp.async.cg.shared.global [%0], [%1], 16;" :: "r"(sa), "l"(ga));
}
#define CP_COMMIT() asm volatile("cp.async.commit_group;" ::: "memory")
#define CP_WAIT1()  asm volatile("cp.async.wait_group 1;" ::: "memory")
#define CP_WAIT0()  asm volatile("cp.async.wait_group 0;" ::: "memory")
#define SWZ128(o)   ((o) ^ (((o) >> 3) & 0x70))
#define SWZ256(o)   ((o) ^ (((o) >> 4) & 0x70))

__device__ __forceinline__ void ldmx4(uint32_t* r, uint32_t addr) {
    asm volatile("ldmatrix.sync.aligned.m8n8.x4.shared.b16 {%0,%1,%2,%3}, [%4];"
                 : "=r"(r[0]), "=r"(r[1]), "=r"(r[2]), "=r"(r[3]) : "r"(addr));
}
__device__ __forceinline__ void ldmx4t(uint32_t* r, uint32_t addr) {
    asm volatile("ldmatrix.sync.aligned.m8n8.x4.trans.shared.b16 {%0,%1,%2,%3}, [%4];"
                 : "=r"(r[0]), "=r"(r[1]), "=r"(r[2]), "=r"(r[3]) : "r"(addr));
}
__device__ __forceinline__ void mma16816h(float* d, const uint32_t* a, uint32_t b0, uint32_t b1) {
    asm volatile("mma.sync.aligned.m16n8k16.row.col.f32.f16.f16.f32 "
                 "{%0,%1,%2,%3},{%4,%5,%6,%7},{%8,%9},{%0,%1,%2,%3};"
                 : "+f"(d[0]), "+f"(d[1]), "+f"(d[2]), "+f"(d[3])
                 : "r"(a[0]), "r"(a[1]), "r"(a[2]), "r"(a[3]), "r"(b0), "r"(b1));
}
__device__ __forceinline__ void mma16816b(float* d, const uint32_t* a, uint32_t b0, uint32_t b1) {
    asm volatile("mma.sync.aligned.m16n8k16.row.col.f32.bf16.bf16.f32 "
                 "{%0,%1,%2,%3},{%4,%5,%6,%7},{%8,%9},{%0,%1,%2,%3};"
                 : "+f"(d[0]), "+f"(d[1]), "+f"(d[2]), "+f"(d[3])
                 : "r"(a[0]), "r"(a[1]), "r"(a[2]), "r"(a[3]), "r"(b0), "r"(b1));
}

#define STG_ROWH 136   /* stage row stride in halves (272B): conflict-free, 16B-aligned */

// ---------------------------------------------------------------------------
// 0) merged setup: weight hi/lo split (blocks 0..2303) + twiddle tables (last)
// ---------------------------------------------------------------------------
__global__ __launch_bounds__(256) void setup_kernel(
    const float* __restrict__ qkv_w, const float* __restrict__ proj_w)
{
    if (blockIdx.x < 2304) {
        int i = blockIdx.x * 256 + threadIdx.x;
        if (i >= CDIM * CDIM) return;
        int r = i / CDIM, c = i % CDIM;
        {
            float v = proj_w[i];
            __nv_bfloat16 h = __float2bfloat16(v);
            g_Wp[(size_t)r * 1536 + c] = h;
            g_Wp[(size_t)r * 1536 + 768 + c] = __float2bfloat16(v - __bfloat162float(h));
        }
        {
            float v = qkv_w[(size_t)(2 * CDIM + r) * CDIM + c];
            __nv_bfloat16 h = __float2bfloat16(v);
            g_Wq[i] = h;
            g_Wq[(size_t)CDIM * CDIM + i] = __float2bfloat16(v - __bfloat162float(h));
        }
    } else {
        __shared__ float cb[64], sb_[64];
        int tid = threadIdx.x;
        const double TWO_PI = 6.283185307179586476925286766559;
        if (tid < 64) {
            double ang = TWO_PI * (double)tid / 64.0;
            cb[tid] = (float)cos(ang);
            sb_[tid] = (float)sin(ang);
        }
        __syncthreads();
        for (int i = tid; i < 128 * 64; i += 256) {
            int row = i >> 6, s = i & 63;
            int idx = ((row & 63) * s) & 63;
            g_T1h[i] = __float2half_rn((row < 64) ? cb[idx] : sb_[idx]);
        }
        for (int i = tid; i < 64 * 128; i += 256) {
            int p = i >> 7, k = i & 127;
            int idx = (p * (k & 63)) & 63;
            g_T2h[i] = __float2half_rn((k < 64) ? cb[idx] : -sb_[idx]);
        }
    }
}

// ---------------------------------------------------------------------------
// 1) B build via bf16 split 3-term mma GEMM:
//    g_Bh[n][k] = fp16( sum_j proj_w[n][j] * qkv_w[2C+j][k] )
//    CTA 64(n) x 64(k), K logical 2304, 36 K-tiles, 2-stage ring.
//    144 CTAs (one full wave). 8 warps as 4m x 2n, warp tile 16x32.
// ---------------------------------------------------------------------------
#define CB_SMEM (2 * 16384)

__device__ __forceinline__ void cb_load_tile(uint32_t sb, int tid, int bm, int bk,
                                             int kt, int slot) {
    int seg = kt / 12;
    int jl = (kt % 12) * 64;
    int aoff = ((seg == 2) ? 768 : 0) + jl;
    size_t qbase = (seg == 1) ? (size_t)CDIM * CDIM : 0;
    uint32_t abase = sb + slot * 16384;
    uint32_t bbase = abase + 8192;
    // A: 64 n-rows x 64 j (128B rows), 512 chunks
#pragma unroll
    for (int c = 0; c < 2; c++) {
        int ch = tid + c * 256;               // 0..511
        int row = ch >> 3, kc = ch & 7;
        cp_async16(abase + SWZ128(row * 128 + kc * 16),
                   g_Wp + (size_t)(bm + row) * 1536 + aoff + kc * 8);
    }
    // B: 64 j-rows x 64 k (128B rows), 512 chunks
#pragma unroll
    for (int c = 0; c < 2; c++) {
        int ch = tid + c * 256;
        int row = ch >> 3, kc = ch & 7;
        cp_async16(bbase + SWZ128(row * 128 + kc * 16),
                   g_Wq + qbase + (size_t)(jl + row) * CDIM + bk + kc * 8);
    }
}

__global__ __launch_bounds__(256) void compute_B_kernel() {
    extern __shared__ char smem[];
    uint32_t sb = smem_u32(smem);
    int bm = blockIdx.y * 64, bk = blockIdx.x * 64;
    int tid = threadIdx.x;
    int wid = tid >> 5, lane = tid & 31;
    int wm = wid >> 1, wn = wid & 1;

    int l7 = lane & 7, sel = lane >> 3;
    int rsel = (sel & 1) * 8;
    int csel = (sel >> 1) * 16;
    int g1 = (lane >> 3) & 1;
    int g2 = (lane >> 4) * 16;

    float acc[4][4];
#pragma unroll
    for (int j = 0; j < 4; j++)
#pragma unroll
        for (int v = 0; v < 4; v++) acc[j][v] = 0.f;

    cb_load_tile(sb, tid, bm, bk, 0, 0);
    CP_COMMIT();

    for (int kt = 0; kt < 36; kt++) {
        if (kt + 1 < 36) {
            cb_load_tile(sb, tid, bm, bk, kt + 1, (kt + 1) & 1);
            CP_COMMIT();
            CP_WAIT1();
        } else {
            CP_WAIT0();
        }
        __syncthreads();

        uint32_t ab = sb + (kt & 1) * 16384;
        uint32_t bb = ab + 8192;
#pragma unroll
        for (int ks = 0; ks < 4; ks++) {
            uint32_t afrag[4];
            {
                int row = wm * 16 + l7 + rsel;
                ldmx4(afrag, ab + SWZ128(row * 128 + ks * 32 + csel));
            }
#pragma unroll
            for (int ng = 0; ng < 2; ng++) {
                uint32_t bfrag[4];
                int row = ks * 16 + l7 + g1 * 8;
                int colb = wn * 64 + ng * 32 + g2;
                ldmx4t(bfrag, bb + SWZ128(row * 128 + colb));
                mma16816b(acc[ng * 2 + 0], afrag, bfrag[0], bfrag[1]);
                mma16816b(acc[ng * 2 + 1], afrag, bfrag[2], bfrag[3]);
            }
        }
        __syncthreads();
    }

    int rq = lane >> 2, cq = (lane & 3) * 2;
#pragma unroll
    for (int n8 = 0; n8 < 4; n8++) {
        float* d = acc[n8];
        int n0 = bm + wm * 16 + rq;
        int k = bk + wn * 32 + n8 * 8 + cq;
        *(__half2*)(g_Bh + (size_t)n0 * CDIM + k) = __floats2half2_rn(d[0], d[1]);
        *(__half2*)(g_Bh + (size_t)(n0 + 8) * CDIM + k) = __floats2half2_rn(d[2], d[3]);
    }
}

// ---------------------------------------------------------------------------
// 2) x -> fp16 (8 floats -> 16B store per thread)
// ---------------------------------------------------------------------------
__global__ __launch_bounds__(256) void prep_a_kernel(const float* __restrict__ x) {
    size_t i8 = ((size_t)blockIdx.x * 256 + threadIdx.x) * 8;
    if (i8 >= (size_t)BATCH * NTOK * CDIM) return;
    float4 v0 = *(const float4*)(x + i8);
    float4 v1 = *(const float4*)(x + i8 + 4);
    __half2 h[4];
    h[0] = __floats2half2_rn(v0.x, v0.y);
    h[1] = __floats2half2_rn(v0.z, v0.w);
    h[2] = __floats2half2_rn(v1.x, v1.y);
    h[3] = __floats2half2_rn(v1.z, v1.w);
    *(uint4*)(g_Ah + i8) = *(uint4*)h;
}

// ---------------------------------------------------------------------------
// 3) Fused GEMM + pass1. CTA tile 128(M) x 128(N), K-tile 64, 3-stage ring.
//    256 threads, 8 warps as 4m x 2n, warp tile 32x64. 2 CTAs/SM.
//    Epilogue: Z fp16 -> smem stage -> fused U = T1 * Z -> g_Uh.
// ---------------------------------------------------------------------------
#define GM_NT 12
#define STG_BYTES 32768          /* A 16KB + B 16KB per stage */
#define NSTAGE 3
#define GM_SMEM (NSTAGE * STG_BYTES + 16384)   /* + T1 (16KB) = 114688 */

__device__ __forceinline__ void gemm_load_tile(uint32_t sb, int tid, int bm, int bn,
                                               int kt, int slot) {
    int koff = kt * 64;
    uint32_t abase = sb + slot * STG_BYTES;
    uint32_t bbase = abase + 16384;
#pragma unroll
    for (int c = 0; c < 4; c++) {
        int ch = tid + c * 256;               // 0..1023: 128 rows x 8 chunks
        int row = ch >> 3, kc = ch & 7;
        cp_async16(abase + SWZ128(row * 128 + kc * 16),
                   g_Ah + (size_t)(bm + row) * CDIM + koff + kc * 8);
    }
#pragma unroll
    for (int c = 0; c < 4; c++) {
        int ch = tid + c * 256;
        int row = ch >> 3, kc = ch & 7;
        cp_async16(bbase + SWZ128(row * 128 + kc * 16),
                   g_Bh + (size_t)(bn + row) * CDIM + koff + kc * 8);
    }
}

__global__ __launch_bounds__(256, 2) void gemm_mma_kernel() {
    extern __shared__ char smem[];
    uint32_t sb = smem_u32(smem);
    uint32_t sbT1 = sb + NSTAGE * STG_BYTES;
    __half* stage1 = (__half*)smem;                            // Z tile (34816B)
    __half* stage2 = (__half*)(smem + 128 * STG_ROWH * 2);     // U tile (34816B)
    uint32_t sbS1 = sb;
    int tid = threadIdx.x;
    int wid = tid >> 5, lane = tid & 31;
    int wm = wid >> 1, wn = wid & 1;
    int bm = blockIdx.y * 128;
    int bn = blockIdx.x * 128;
    int b = bm >> 12;                 // batch
    int r0 = (bm >> 6) & 63;          // first spatial row of this tile

    int l7 = lane & 7, sel = lane >> 3;
    int rsel = (sel & 1) * 8;
    int csel = (sel >> 1) * 16;
    int g1 = (lane >> 3) & 1;
    int g2 = (lane >> 4) * 16;

    float acc[2][8][4];
#pragma unroll
    for (int i = 0; i < 2; i++)
#pragma unroll
        for (int j = 0; j < 8; j++)
#pragma unroll
            for (int v = 0; v < 4; v++) acc[i][j][v] = 0.f;

    // prologue: T1 + tile0 in group 0; tile1 in group 1
#pragma unroll
    for (int c = 0; c < 4; c++) {
        int o = (tid + c * 256) * 16;       // 0..16383
        cp_async16(sbT1 + SWZ128(o), (const char*)g_T1h + o);
    }
    gemm_load_tile(sb, tid, bm, bn, 0, 0);
    CP_COMMIT();
    gemm_load_tile(sb, tid, bm, bn, 1, 1);
    CP_COMMIT();

    for (int kt = 0; kt < GM_NT; kt++) {
        CP_WAIT1();
        __syncthreads();

        if (kt + NSTAGE - 1 < GM_NT)
            gemm_load_tile(sb, tid, bm, bn, kt + NSTAGE - 1, (kt + NSTAGE - 1) % NSTAGE);
        CP_COMMIT();

        uint32_t ab = sb + (kt % NSTAGE) * STG_BYTES;
        uint32_t bb = ab + 16384;
#pragma unroll
        for (int ks = 0; ks < 4; ks++) {
            uint32_t afrag[2][4];
#pragma unroll
            for (int mt = 0; mt < 2; mt++) {
                int row = wm * 32 + mt * 16 + l7 + rsel;
                ldmx4(afrag[mt], ab + SWZ128(row * 128 + ks * 32 + csel));
            }
#pragma unroll
            for (int nt = 0; nt < 4; nt++) {
                uint32_t bfrag[4];
                int row = wn * 64 + nt * 16 + l7 + rsel;
                ldmx4(bfrag, bb + SWZ128(row * 128 + ks * 32 + csel));
#pragma unroll
                for (int mt = 0; mt < 2; mt++) {
                    mma16816h(acc[mt][nt * 2 + 0], afrag[mt], bfrag[0], bfrag[2]);
                    mma16816h(acc[mt][nt * 2 + 1], afrag[mt], bfrag[1], bfrag[3]);
                }
            }
        }
    }

    // ---- stage Z (fp16) into stage1 ----
    CP_WAIT0();
    __syncthreads();
    int rq = lane >> 2, cq = (lane & 3) * 2;
#pragma unroll
    for (int mt = 0; mt < 2; mt++) {
#pragma unroll
        for (int n8 = 0; n8 < 8; n8++) {
            float* d = acc[mt][n8];
            int row = wm * 32 + mt * 16 + rq;
            int c = wn * 64 + n8 * 8 + cq;
            *(__half2*)&stage1[row * STG_ROWH + c] = __floats2half2_rn(d[0], d[1]);
            *(__half2*)&stage1[(row + 8) * STG_ROWH + c] = __floats2half2_rn(d[2], d[3]);
        }
    }
    __syncthreads();

    // ---- fused pass1: per half h (spatial row r0+h): U[128i x 128ch] = T1 * Z_h ----
#pragma unroll
    for (int h = 0; h < 2; h++) {
        float uacc[2][8][4];
#pragma unroll
        for (int i = 0; i < 2; i++)
#pragma unroll
            for (int j = 0; j < 8; j++)
#pragma unroll
                for (int v = 0; v < 4; v++) uacc[i][j][v] = 0.f;

#pragma unroll
        for (int ks = 0; ks < 4; ks++) {
            uint32_t afrag[2][4];
#pragma unroll
            for (int mt = 0; mt < 2; mt++) {
                int row = wm * 32 + mt * 16 + l7 + rsel;
                ldmx4(afrag[mt], sbT1 + SWZ128(row * 128 + ks * 32 + csel));
            }
#pragma unroll
            for (int ng = 0; ng < 4; ng++) {
                uint32_t bfrag[4];
                int srow = h * 64 + ks * 16 + l7 + g1 * 8;
                int colb = wn * 128 + ng * 32 + g2;
                ldmx4t(bfrag, sbS1 + srow * (STG_ROWH * 2) + colb);
#pragma unroll
                for (int mt = 0; mt < 2; mt++) {
                    mma16816h(uacc[mt][ng * 2 + 0], afrag[mt], bfrag[0], bfrag[1]);
                    mma16816h(uacc[mt][ng * 2 + 1], afrag[mt], bfrag[2], bfrag[3]);
                }
            }
        }

        if (h == 1) __syncthreads();      // prior stage2 store-read complete
#pragma unroll
        for (int mt = 0; mt < 2; mt++) {
#pragma unroll
            for (int n8 = 0; n8 < 8; n8++) {
                float* d = uacc[mt][n8];
                int i0 = wm * 32 + mt * 16 + rq;
                int chl = wn * 64 + n8 * 8 + cq;
                *(__half2*)&stage2[i0 * STG_ROWH + chl] = __floats2half2_rn(d[0], d[1]);
                *(__half2*)&stage2[(i0 + 8) * STG_ROWH + chl] = __floats2half2_rn(d[2], d[3]);
            }
        }
        __syncthreads();
        int r = r0 + h;
#pragma unroll
        for (int it = 0; it < 8; it++) {
            int idx = tid + it * 256;             // 0..2047: 128 rows x 16 chunks
            int row = idx >> 4, ck = idx & 15;
            int q = row & 63;
            int kk = (row < 64) ? r : 64 + r;
            uint4 v = *(uint4*)&stage2[row * STG_ROWH + ck * 8];
            *(uint4*)(g_Uh + ((size_t)(b * 64 + q) * 128 + kk) * CDIM + bn + ck * 8) = v;
        }
    }
}

// ---------------------------------------------------------------------------
// 4) Pass 2: grid (6 cht, 16 qg, 8 b). Each CTA loads T2 once and loops over
//    4 q values with double-buffered U. out[64p x 128ch] = T2 * U + bias.
// ---------------------------------------------------------------------------
#define P2_SMEM (16384 + 2 * 32768)

__global__ __launch_bounds__(256) void pass2_kernel(
    const float* __restrict__ bias, float* __restrict__ out)
{
    extern __shared__ char smem[];
    uint32_t sb = smem_u32(smem);
    uint32_t sbA = sb;
    int cht = blockIdx.x, qg = blockIdx.y, b = blockIdx.z;
    int c0 = cht * 128;
    int q0 = qg * 4;
    int tid = threadIdx.x;
    int wid = tid >> 5, lane = tid & 31;
    int wm = wid >> 2, wn = wid & 3;

    // prologue: A (T2) + U(q0) -> group 0
#pragma unroll
    for (int c = 0; c < 4; c++) {
        int idx = tid + c * 256;
        int p = idx >> 4, ck = idx & 15;
        cp_async16(sbA + SWZ256(p * 256 + ck * 16), g_T2h + p * 128 + ck * 8);
    }
    {
        const __half* usrc = g_Uh + (size_t)(b * 64 + q0) * 128 * CDIM;
#pragma unroll
        for (int c = 0; c < 8; c++) {
            int idx = tid + c * 256;
            int k = idx >> 4, ck = idx & 15;
            cp_async16(sb + 16384 + SWZ256(k * 256 + ck * 16),
                       usrc + (size_t)k * CDIM + c0 + ck * 8);
        }
    }
    CP_COMMIT();

    int l7 = lane & 7, sel = lane >> 3;
    int rsel = (sel & 1) * 8;
    int csel = (sel >> 1) * 16;
    int g1 = (lane >> 3) & 1;
    int g2 = (lane >> 4) * 16;

    for (int iq = 0; iq < 4; iq++) {
        __syncthreads();
        if (iq + 1 < 4) {
            uint32_t bbuf = sb + 16384 + ((iq + 1) & 1) * 32768;
            const __half* usrc = g_Uh + (size_t)(b * 64 + q0 + iq + 1) * 128 * CDIM;
#pragma unroll
            for (int c = 0; c < 8; c++) {
                int idx = tid + c * 256;
                int k = idx >> 4, ck = idx & 15;
                cp_async16(bbuf + SWZ256(k * 256 + ck * 16),
                           usrc + (size_t)k * CDIM + c0 + ck * 8);
            }
            CP_COMMIT();
            CP_WAIT1();
        } else {
            CP_WAIT0();
        }
        __syncthreads();

        uint32_t sbB = sb + 16384 + (iq & 1) * 32768;
        int q = q0 + iq;

        float acc[2][4][4];
#pragma unroll
        for (int i = 0; i < 2; i++)
#pragma unroll
            for (int j = 0; j < 4; j++)
#pragma unroll
                for (int v = 0; v < 4; v++) acc[i][j][v] = 0.f;

#pragma unroll
        for (int ks = 0; ks < 8; ks++) {
            uint32_t afrag[2][4];
#pragma unroll
            for (int mt = 0; mt < 2; mt++) {
                int row = wm * 32 + mt * 16 + l7 + rsel;
                ldmx4(afrag[mt], sbA + SWZ256(row * 256 + ks * 32 + csel));
            }
#pragma unroll
            for (int ng = 0; ng < 2; ng++) {
                uint32_t bfrag[4];
                int row = ks * 16 + l7 + g1 * 8;
                int colb = wn * 64 + ng * 32 + g2;
                ldmx4t(bfrag, sbB + SWZ256(row * 256 + colb));
#pragma unroll
                for (int mt = 0; mt < 2; mt++) {
                    mma16816h(acc[mt][ng * 2 + 0], afrag[mt], bfrag[0], bfrag[1]);
                    mma16816h(acc[mt][ng * 2 + 1], afrag[mt], bfrag[2], bfrag[3]);
                }
            }
        }

        int rq = lane >> 2, cq = (lane & 3) * 2;
#pragma unroll
        for (int mt = 0; mt < 2; mt++) {
            int pbase = wm * 32 + mt * 16;
#pragma unroll
            for (int n8 = 0; n8 < 4; n8++) {
                float* d = acc[mt][n8];
                int ch = c0 + wn * 32 + n8 * 8 + cq;
                float2 bv = *(const float2*)(bias + ch);
                int p0 = pbase + rq, p1 = pbase + rq + 8;
                float* o0 = out + ((size_t)b * NTOK + p0 * 64 + q) * CDIM + ch;
                float* o1 = out + ((size_t)b * NTOK + p1 * 64 + q) * CDIM + ch;
                *(float2*)o0 = make_float2(d[0] + bv.x, d[1] + bv.y);
                *(float2*)o1 = make_float2(d[2] + bv.x, d[3] + bv.y);
            }
        }
    }
}

// ---------------------------------------------------------------------------
// launch
// ---------------------------------------------------------------------------
extern "C" void kernel_launch(void* const* d_in, const int* in_sizes, int n_in,
                              void* d_out, int out_size)
{
    const float* x      = (const float*)d_in[0];   // [8,4096,768]
    const float* qkv_w  = (const float*)d_in[1];   // [2304,768]
    const float* proj_w = (const float*)d_in[2];   // [768,768]
    const float* proj_b = (const float*)d_in[3];   // [768]
    float* out = (float*)d_out;

    cudaFuncSetAttribute(gemm_mma_kernel,  cudaFuncAttributeMaxDynamicSharedMemorySize, GM_SMEM);
    cudaFuncSetAttribute(pass2_kernel,     cudaFuncAttributeMaxDynamicSharedMemorySize, P2_SMEM);
    cudaFuncSetAttribute(compute_B_kernel, cudaFuncAttributeMaxDynamicSharedMemorySize, CB_SMEM);

    setup_kernel<<<2305, 256>>>(qkv_w, proj_w);
    compute_B_kernel<<<dim3(CDIM / 64, CDIM / 64), 256, CB_SMEM>>>();
    prep_a_kernel<<<(int)(((size_t)BATCH * NTOK * CDIM / 8 + 255) / 256), 256>>>(x);
    gemm_mma_kernel<<<dim3(CDIM / 128, (BATCH * NTOK) / 128), 256, GM_SMEM>>>();
    pass2_kernel<<<dim3(6, 16, BATCH), 256, P2_SMEM>>>(proj_b, out);
}